// round 1
// baseline (speedup 1.0000x reference)
#include <cuda_runtime.h>

#define N_T1 168            // dow(7) * sex(2) * month(12)
#define N_T2 744            // time(24) * day(31)
#define N_T3 100            // age
#define NE   (N_T1 + N_T2 + N_T3)   // 1012
#define PSTRIDE 36          // floats per entry, padded (36*4B=144B, 16B-aligned, breaks bank conflicts)

// Scratch for pre-projected fused tables (no cudaMalloc allowed).
__device__ float4 g_proj4[NE * (PSTRIDE / 4)];

__global__ void precompute_kernel(const float* __restrict__ emb_dow,
                                  const float* __restrict__ emb_time,
                                  const float* __restrict__ emb_sex,
                                  const float* __restrict__ emb_age,
                                  const float* __restrict__ emb_month,
                                  const float* __restrict__ emb_day,
                                  const float* __restrict__ W,
                                  const float* __restrict__ b) {
    int t = blockIdx.x * blockDim.x + threadIdx.x;
    if (t >= NE * 32) return;
    int e = t >> 5;
    int f = t & 31;
    float v = 0.f;
    // W row layout follows concat order: dow[0:4) time[4:8) sex[8:12) age[12:16) month[16:20) day[20:24)
    if (e < N_T1) {
        int d = e / 24, rem = e % 24;
        int s = rem / 12, m = rem % 12;
        #pragma unroll
        for (int j = 0; j < 4; j++) {
            v = fmaf(emb_dow[d * 4 + j],   W[(0 + j) * 32 + f], v);
            v = fmaf(emb_sex[s * 4 + j],   W[(8 + j) * 32 + f], v);
            v = fmaf(emb_month[m * 4 + j], W[(16 + j) * 32 + f], v);
        }
    } else if (e < N_T1 + N_T2) {
        int e2 = e - N_T1;
        int tm = e2 / 31, dy = e2 % 31;
        #pragma unroll
        for (int j = 0; j < 4; j++) {
            v = fmaf(emb_time[tm * 4 + j], W[(4 + j) * 32 + f], v);
            v = fmaf(emb_day[dy * 4 + j],  W[(20 + j) * 32 + f], v);
        }
    } else {
        int a = e - (N_T1 + N_T2);
        v = b[f];
        #pragma unroll
        for (int j = 0; j < 4; j++)
            v = fmaf(emb_age[a * 4 + j], W[(12 + j) * 32 + f], v);
    }
    reinterpret_cast<float*>(g_proj4)[e * PSTRIDE + f] = v;
}

__global__ __launch_bounds__(1024, 1)
void mf_main_kernel(const int* __restrict__ dow,
                    const int* __restrict__ tim,
                    const int* __restrict__ sex,
                    const int* __restrict__ age,
                    const int* __restrict__ month,
                    const int* __restrict__ day,
                    const int* __restrict__ dest,
                    const float4* __restrict__ item4,
                    float* __restrict__ out,
                    int n) {
    extern __shared__ float4 sp[];   // NE * (PSTRIDE/4) float4
    // Stage the fused proj tables into shared memory once per CTA.
    for (int i = threadIdx.x; i < NE * (PSTRIDE / 4); i += blockDim.x)
        sp[i] = g_proj4[i];
    __syncthreads();

    for (int i = blockIdx.x * blockDim.x + threadIdx.x; i < n;
         i += gridDim.x * blockDim.x) {
        int i1 = dow[i] * 24 + sex[i] * 12 + month[i];
        int i2 = N_T1 + tim[i] * 31 + day[i];
        int i3 = N_T1 + N_T2 + age[i];
        const float4* __restrict__ p1 = sp + i1 * (PSTRIDE / 4);
        const float4* __restrict__ p2 = sp + i2 * (PSTRIDE / 4);
        const float4* __restrict__ p3 = sp + i3 * (PSTRIDE / 4);
        const float4* __restrict__ it = item4 + (long long)dest[i] * 8;

        float sum = 0.f;
        #pragma unroll 4
        for (int k = 0; k < 8; k++) {
            float4 a = p1[k];
            float4 c = p2[k];
            float4 e = p3[k];
            float4 v = it[k];
            sum = fmaf(a.x + c.x + e.x, v.x, sum);
            sum = fmaf(a.y + c.y + e.y, v.y, sum);
            sum = fmaf(a.z + c.z + e.z, v.z, sum);
            sum = fmaf(a.w + c.w + e.w, v.w, sum);
        }
        out[i] = sum;
    }
}

extern "C" void kernel_launch(void* const* d_in, const int* in_sizes, int n_in,
                              void* d_out, int out_size) {
    // Input order (metadata): dayofweek, time, sex, age, month, day, destination,
    // emb_dow, emb_time, emb_sex, emb_age, emb_month, emb_day, W, b, item_table
    const int* dow   = (const int*)d_in[0];
    const int* tim   = (const int*)d_in[1];
    const int* sex   = (const int*)d_in[2];
    const int* age   = (const int*)d_in[3];
    const int* month = (const int*)d_in[4];
    const int* day   = (const int*)d_in[5];
    const int* dest  = (const int*)d_in[6];
    const float* emb_dow   = (const float*)d_in[7];
    const float* emb_time  = (const float*)d_in[8];
    const float* emb_sex   = (const float*)d_in[9];
    const float* emb_age   = (const float*)d_in[10];
    const float* emb_month = (const float*)d_in[11];
    const float* emb_day   = (const float*)d_in[12];
    const float* W = (const float*)d_in[13];
    const float* b = (const float*)d_in[14];
    const float4* item4 = (const float4*)d_in[15];
    float* out = (float*)d_out;
    int n = in_sizes[0];

    // 1) Build fused pre-projected tables (1012 x 32, padded stride 36).
    int pre_threads = NE * 32;
    precompute_kernel<<<(pre_threads + 255) / 256, 256>>>(
        emb_dow, emb_time, emb_sex, emb_age, emb_month, emb_day, W, b);

    // 2) Main gather + dot kernel. 145,728 B dynamic smem -> opt-in required.
    int smem_bytes = NE * PSTRIDE * (int)sizeof(float);
    cudaFuncSetAttribute(mf_main_kernel,
                         cudaFuncAttributeMaxDynamicSharedMemorySize, smem_bytes);
    mf_main_kernel<<<152, 1024, smem_bytes>>>(
        dow, tim, sex, age, month, day, dest, item4, out, n);
}

// round 2
// speedup vs baseline: 2.3393x; 2.3393x over previous
#include <cuda_runtime.h>

#define N_T1 168            // dow(7) * sex(2) * month(12)
#define N_T2 744            // time(24) * day(31)
#define N_T3 100            // age
#define NE   (N_T1 + N_T2 + N_T3)   // 1012
// Entry stride = 32 floats = 128 B, aligned; cooperative 8-lane reads are conflict-free.

// Scratch for pre-projected fused tables (no cudaMalloc allowed).
__device__ float4 g_proj4[NE * 8];

__global__ void precompute_kernel(const float* __restrict__ emb_dow,
                                  const float* __restrict__ emb_time,
                                  const float* __restrict__ emb_sex,
                                  const float* __restrict__ emb_age,
                                  const float* __restrict__ emb_month,
                                  const float* __restrict__ emb_day,
                                  const float* __restrict__ W,
                                  const float* __restrict__ b) {
    int t = blockIdx.x * blockDim.x + threadIdx.x;
    if (t >= NE * 32) return;
    int e = t >> 5;
    int f = t & 31;
    float v = 0.f;
    // W row layout follows concat order: dow[0:4) time[4:8) sex[8:12) age[12:16) month[16:20) day[20:24)
    if (e < N_T1) {
        int d = e / 24, rem = e % 24;
        int s = rem / 12, m = rem % 12;
        #pragma unroll
        for (int j = 0; j < 4; j++) {
            v = fmaf(emb_dow[d * 4 + j],   W[(0 + j) * 32 + f], v);
            v = fmaf(emb_sex[s * 4 + j],   W[(8 + j) * 32 + f], v);
            v = fmaf(emb_month[m * 4 + j], W[(16 + j) * 32 + f], v);
        }
    } else if (e < N_T1 + N_T2) {
        int e2 = e - N_T1;
        int tm = e2 / 31, dy = e2 % 31;
        #pragma unroll
        for (int j = 0; j < 4; j++) {
            v = fmaf(emb_time[tm * 4 + j], W[(4 + j) * 32 + f], v);
            v = fmaf(emb_day[dy * 4 + j],  W[(20 + j) * 32 + f], v);
        }
    } else {
        int a = e - (N_T1 + N_T2);
        v = b[f];
        #pragma unroll
        for (int j = 0; j < 4; j++)
            v = fmaf(emb_age[a * 4 + j], W[(12 + j) * 32 + f], v);
    }
    reinterpret_cast<float*>(g_proj4)[e * 32 + f] = v;
}

__global__ __launch_bounds__(1024, 1)
void mf_main_kernel(const int* __restrict__ dow,
                    const int* __restrict__ tim,
                    const int* __restrict__ sex,
                    const int* __restrict__ age,
                    const int* __restrict__ month,
                    const int* __restrict__ day,
                    const int* __restrict__ dest,
                    const float4* __restrict__ item4,
                    float* __restrict__ out,
                    int n) {
    extern __shared__ float4 sp[];   // NE * 8 float4 = 129,536 B
    // Stage the fused proj tables into shared memory once per CTA.
    for (int i = threadIdx.x; i < NE * 8; i += blockDim.x)
        sp[i] = g_proj4[i];
    __syncthreads();

    const int lane = threadIdx.x & 31;
    const int warp = threadIdx.x >> 5;
    const int sub  = lane & 7;        // position within 8-lane group
    const int grp  = lane >> 3;       // group id 0..3

    const int warpsTotal = gridDim.x * (blockDim.x >> 5);
    const int gwarp = blockIdx.x * (blockDim.x >> 5) + warp;

    for (int base = gwarp * 32; base < n; base += warpsTotal * 32) {
        // Phase A: each lane loads its own row's indices (fully coalesced),
        // packs the three table indices into one int.
        int r = base + lane;
        int pk = 0, dd = 0;
        if (r < n) {
            int i1 = dow[r] * 24 + sex[r] * 12 + month[r];   // 0..167  (8 bits)
            int t2 = tim[r] * 31 + day[r];                   // 0..743  (10 bits)
            int a3 = age[r];                                 // 0..99   (7 bits)
            pk = i1 | (t2 << 8) | (a3 << 18);
            dd = dest[r];
        }

        // Phase B: 8 sub-iterations; each processes 4 rows with 8 lanes/row.
        #pragma unroll
        for (int s = 0; s < 8; s++) {
            int src = s * 4 + grp;                 // row handled by this group
            int pks = __shfl_sync(0xffffffffu, pk, src);
            int dds = __shfl_sync(0xffffffffu, dd, src);
            int j1 = pks & 255;
            int j2 = N_T1 + ((pks >> 8) & 1023);
            int j3 = N_T1 + N_T2 + ((pks >> 18) & 127);

            // 8 lanes read 8 consecutive float4s = one 128B entry: conflict-free.
            float4 a = sp[j1 * 8 + sub];
            float4 c = sp[j2 * 8 + sub];
            float4 e = sp[j3 * 8 + sub];
            float4 v = __ldg(item4 + (size_t)dds * 8 + sub);  // 128B coalesced/row

            float p = fmaf(a.x + c.x + e.x, v.x,
                      fmaf(a.y + c.y + e.y, v.y,
                      fmaf(a.z + c.z + e.z, v.z,
                           (a.w + c.w + e.w) * v.w)));

            // Reduce across the 8-lane group.
            p += __shfl_xor_sync(0xffffffffu, p, 4);
            p += __shfl_xor_sync(0xffffffffu, p, 2);
            p += __shfl_xor_sync(0xffffffffu, p, 1);

            int row = base + src;
            if (sub == 0 && row < n)
                out[row] = p;
        }
    }
}

extern "C" void kernel_launch(void* const* d_in, const int* in_sizes, int n_in,
                              void* d_out, int out_size) {
    // Input order: dayofweek, time, sex, age, month, day, destination,
    // emb_dow, emb_time, emb_sex, emb_age, emb_month, emb_day, W, b, item_table
    const int* dow   = (const int*)d_in[0];
    const int* tim   = (const int*)d_in[1];
    const int* sex   = (const int*)d_in[2];
    const int* age   = (const int*)d_in[3];
    const int* month = (const int*)d_in[4];
    const int* day   = (const int*)d_in[5];
    const int* dest  = (const int*)d_in[6];
    const float* emb_dow   = (const float*)d_in[7];
    const float* emb_time  = (const float*)d_in[8];
    const float* emb_sex   = (const float*)d_in[9];
    const float* emb_age   = (const float*)d_in[10];
    const float* emb_month = (const float*)d_in[11];
    const float* emb_day   = (const float*)d_in[12];
    const float* W = (const float*)d_in[13];
    const float* b = (const float*)d_in[14];
    const float4* item4 = (const float4*)d_in[15];
    float* out = (float*)d_out;
    int n = in_sizes[0];

    // 1) Build fused pre-projected tables (1012 x 32, stride 32).
    int pre_threads = NE * 32;
    precompute_kernel<<<(pre_threads + 255) / 256, 256>>>(
        emb_dow, emb_time, emb_sex, emb_age, emb_month, emb_day, W, b);

    // 2) Main gather + dot kernel. 129,536 B dynamic smem -> opt-in required.
    int smem_bytes = NE * 32 * (int)sizeof(float);
    cudaFuncSetAttribute(mf_main_kernel,
                         cudaFuncAttributeMaxDynamicSharedMemorySize, smem_bytes);
    mf_main_kernel<<<152, 1024, smem_bytes>>>(
        dow, tim, sex, age, month, day, dest, item4, out, n);
}

// round 3
// speedup vs baseline: 2.4358x; 1.0413x over previous
#include <cuda_runtime.h>
#include <cuda_fp16.h>

#define N_T1 168            // dow(7) * sex(2) * month(12)
#define N_T2 744            // time(24) * day(31)
#define N_T3 100            // age
#define NE   (N_T1 + N_T2 + N_T3)   // 1012

// Pre-projected fused tables in fp16: entry = 32 halves = 64 B = 4 x uint4.
__device__ uint4 g_projh4[NE * 4];

__global__ void precompute_kernel(const float* __restrict__ emb_dow,
                                  const float* __restrict__ emb_time,
                                  const float* __restrict__ emb_sex,
                                  const float* __restrict__ emb_age,
                                  const float* __restrict__ emb_month,
                                  const float* __restrict__ emb_day,
                                  const float* __restrict__ W,
                                  const float* __restrict__ b) {
    int t = blockIdx.x * blockDim.x + threadIdx.x;
    if (t >= NE * 32) return;
    int e = t >> 5;
    int f = t & 31;
    float v = 0.f;
    // W row layout follows concat order: dow[0:4) time[4:8) sex[8:12) age[12:16) month[16:20) day[20:24)
    if (e < N_T1) {
        int d = e / 24, rem = e % 24;
        int s = rem / 12, m = rem % 12;
        #pragma unroll
        for (int j = 0; j < 4; j++) {
            v = fmaf(emb_dow[d * 4 + j],   W[(0 + j) * 32 + f], v);
            v = fmaf(emb_sex[s * 4 + j],   W[(8 + j) * 32 + f], v);
            v = fmaf(emb_month[m * 4 + j], W[(16 + j) * 32 + f], v);
        }
    } else if (e < N_T1 + N_T2) {
        int e2 = e - N_T1;
        int tm = e2 / 31, dy = e2 % 31;
        #pragma unroll
        for (int j = 0; j < 4; j++) {
            v = fmaf(emb_time[tm * 4 + j], W[(4 + j) * 32 + f], v);
            v = fmaf(emb_day[dy * 4 + j],  W[(20 + j) * 32 + f], v);
        }
    } else {
        int a = e - (N_T1 + N_T2);
        v = b[f];
        #pragma unroll
        for (int j = 0; j < 4; j++)
            v = fmaf(emb_age[a * 4 + j], W[(12 + j) * 32 + f], v);
    }
    reinterpret_cast<__half*>(g_projh4)[e * 32 + f] = __float2half_rn(v);
}

__global__ __launch_bounds__(1024, 1)
void mf_main_kernel(const int* __restrict__ dow,
                    const int* __restrict__ tim,
                    const int* __restrict__ sex,
                    const int* __restrict__ age,
                    const int* __restrict__ month,
                    const int* __restrict__ day,
                    const int* __restrict__ dest,
                    const float4* __restrict__ item4,
                    float* __restrict__ out,
                    int n) {
    extern __shared__ uint4 sp[];   // NE * 4 uint4 = 64,768 B
    // Stage the fused fp16 proj tables into shared memory once per CTA.
    for (int i = threadIdx.x; i < NE * 4; i += blockDim.x)
        sp[i] = g_projh4[i];
    __syncthreads();

    const int lane = threadIdx.x & 31;
    const int warp = threadIdx.x >> 5;
    const int sub  = lane & 3;        // position within 4-lane group (covers 8 factors)
    const int grp  = lane >> 2;       // group id 0..7

    const int warpsTotal = gridDim.x * (blockDim.x >> 5);
    const int gwarp = blockIdx.x * (blockDim.x >> 5) + warp;

    for (int base = gwarp * 32; base < n; base += warpsTotal * 32) {
        // Phase A: each lane loads its own row's indices (fully coalesced),
        // packs the three table indices into one int.
        int r = base + lane;
        int pk = 0, dd = 0;
        if (r < n) {
            int i1 = dow[r] * 24 + sex[r] * 12 + month[r];   // 0..167  (8 bits)
            int t2 = tim[r] * 31 + day[r];                   // 0..743  (10 bits)
            int a3 = age[r];                                 // 0..99   (7 bits)
            pk = i1 | (t2 << 8) | (a3 << 18);
            dd = dest[r];
        }

        // Phase B: 4 sub-iterations; each processes 8 rows with 4 lanes/row.
        #pragma unroll
        for (int s = 0; s < 4; s++) {
            int src = s * 8 + grp;                 // row handled by this group
            int pks = __shfl_sync(0xffffffffu, pk, src);
            int dds = __shfl_sync(0xffffffffu, dd, src);
            int j1 = pks & 255;
            int j2 = N_T1 + ((pks >> 8) & 1023);
            int j3 = N_T1 + N_T2 + ((pks >> 18) & 127);

            // 4 lanes read 4 consecutive uint4s = one 64B fp16 entry: conflict-free.
            uint4 A = sp[j1 * 4 + sub];
            uint4 C = sp[j2 * 4 + sub];
            uint4 E = sp[j3 * 4 + sub];
            const float4* it = item4 + (size_t)dds * 8 + sub * 2;
            float4 v0 = __ldg(it);
            float4 v1 = __ldg(it + 1);

            const __half2* a2 = reinterpret_cast<const __half2*>(&A);
            const __half2* c2 = reinterpret_cast<const __half2*>(&C);
            const __half2* e2 = reinterpret_cast<const __half2*>(&E);

            float2 u0 = __half22float2(a2[0]);
            float2 t0 = __half22float2(c2[0]);
            float2 w0 = __half22float2(e2[0]);
            float2 u1 = __half22float2(a2[1]);
            float2 t1 = __half22float2(c2[1]);
            float2 w1 = __half22float2(e2[1]);
            float2 u2 = __half22float2(a2[2]);
            float2 t2f = __half22float2(c2[2]);
            float2 w2 = __half22float2(e2[2]);
            float2 u3 = __half22float2(a2[3]);
            float2 t3 = __half22float2(c2[3]);
            float2 w3 = __half22float2(e2[3]);

            float p;
            p =          (u0.x + t0.x + w0.x) * v0.x;
            p = fmaf(u0.y + t0.y + w0.y, v0.y, p);
            p = fmaf(u1.x + t1.x + w1.x, v0.z, p);
            p = fmaf(u1.y + t1.y + w1.y, v0.w, p);
            p = fmaf(u2.x + t2f.x + w2.x, v1.x, p);
            p = fmaf(u2.y + t2f.y + w2.y, v1.y, p);
            p = fmaf(u3.x + t3.x + w3.x, v1.z, p);
            p = fmaf(u3.y + t3.y + w3.y, v1.w, p);

            // Reduce across the 4-lane group.
            p += __shfl_xor_sync(0xffffffffu, p, 2);
            p += __shfl_xor_sync(0xffffffffu, p, 1);

            int row = base + src;
            if (sub == 0 && row < n)
                out[row] = p;     // lanes 0,4..28 -> 8 consecutive rows: coalesced
        }
    }
}

extern "C" void kernel_launch(void* const* d_in, const int* in_sizes, int n_in,
                              void* d_out, int out_size) {
    // Input order: dayofweek, time, sex, age, month, day, destination,
    // emb_dow, emb_time, emb_sex, emb_age, emb_month, emb_day, W, b, item_table
    const int* dow   = (const int*)d_in[0];
    const int* tim   = (const int*)d_in[1];
    const int* sex   = (const int*)d_in[2];
    const int* age   = (const int*)d_in[3];
    const int* month = (const int*)d_in[4];
    const int* day   = (const int*)d_in[5];
    const int* dest  = (const int*)d_in[6];
    const float* emb_dow   = (const float*)d_in[7];
    const float* emb_time  = (const float*)d_in[8];
    const float* emb_sex   = (const float*)d_in[9];
    const float* emb_age   = (const float*)d_in[10];
    const float* emb_month = (const float*)d_in[11];
    const float* emb_day   = (const float*)d_in[12];
    const float* W = (const float*)d_in[13];
    const float* b = (const float*)d_in[14];
    const float4* item4 = (const float4*)d_in[15];
    float* out = (float*)d_out;
    int n = in_sizes[0];

    // 1) Build fused pre-projected fp16 tables (1012 x 32).
    int pre_threads = NE * 32;
    precompute_kernel<<<(pre_threads + 255) / 256, 256>>>(
        emb_dow, emb_time, emb_sex, emb_age, emb_month, emb_day, W, b);

    // 2) Main gather + dot kernel. 64,768 B dynamic smem.
    int smem_bytes = NE * 4 * (int)sizeof(uint4);
    cudaFuncSetAttribute(mf_main_kernel,
                         cudaFuncAttributeMaxDynamicSharedMemorySize, smem_bytes);
    mf_main_kernel<<<152, 1024, smem_bytes>>>(
        dow, tim, sex, age, month, day, dest, item4, out, n);
}

// round 4
// speedup vs baseline: 2.8995x; 1.1903x over previous
#include <cuda_runtime.h>
#include <cuda_fp16.h>

#define N_T1 168            // dow(7) * sex(2) * month(12)
#define N_T2 744            // time(24) * day(31)
#define N_T3 100            // age
#define NE   (N_T1 + N_T2 + N_T3)   // 1012

// Pre-projected fused tables in fp16, DUPLICATED per entry:
// entry e occupies 128 B: copy A at [e*128, e*128+64)  -> smem banks 0..15
//                         copy B at [e*128+64, e*128+128) -> smem banks 16..31
__device__ uint4 g_projh[NE * 8];   // NE * 128 B

__global__ void precompute_kernel(const float* __restrict__ emb_dow,
                                  const float* __restrict__ emb_time,
                                  const float* __restrict__ emb_sex,
                                  const float* __restrict__ emb_age,
                                  const float* __restrict__ emb_month,
                                  const float* __restrict__ emb_day,
                                  const float* __restrict__ W,
                                  const float* __restrict__ b) {
    int t = blockIdx.x * blockDim.x + threadIdx.x;
    if (t >= NE * 32) return;
    int e = t >> 5;
    int f = t & 31;
    float v = 0.f;
    // W row layout follows concat order: dow[0:4) time[4:8) sex[8:12) age[12:16) month[16:20) day[20:24)
    if (e < N_T1) {
        int d = e / 24, rem = e % 24;
        int s = rem / 12, m = rem % 12;
        #pragma unroll
        for (int j = 0; j < 4; j++) {
            v = fmaf(emb_dow[d * 4 + j],   W[(0 + j) * 32 + f], v);
            v = fmaf(emb_sex[s * 4 + j],   W[(8 + j) * 32 + f], v);
            v = fmaf(emb_month[m * 4 + j], W[(16 + j) * 32 + f], v);
        }
    } else if (e < N_T1 + N_T2) {
        int e2 = e - N_T1;
        int tm = e2 / 31, dy = e2 % 31;
        #pragma unroll
        for (int j = 0; j < 4; j++) {
            v = fmaf(emb_time[tm * 4 + j], W[(4 + j) * 32 + f], v);
            v = fmaf(emb_day[dy * 4 + j],  W[(20 + j) * 32 + f], v);
        }
    } else {
        int a = e - (N_T1 + N_T2);
        v = b[f];
        #pragma unroll
        for (int j = 0; j < 4; j++)
            v = fmaf(emb_age[a * 4 + j], W[(12 + j) * 32 + f], v);
    }
    __half hv = __float2half_rn(v);
    __half* base = reinterpret_cast<__half*>(g_projh) + e * 64;
    base[f]      = hv;   // copy A
    base[32 + f] = hv;   // copy B
}

__global__ __launch_bounds__(1024, 1)
void mf_main_kernel(const int* __restrict__ dow,
                    const int* __restrict__ tim,
                    const int* __restrict__ sex,
                    const int* __restrict__ age,
                    const int* __restrict__ month,
                    const int* __restrict__ day,
                    const int* __restrict__ dest,
                    const float4* __restrict__ item4,
                    float* __restrict__ out,
                    int n) {
    extern __shared__ uint4 sp[];   // NE * 8 uint4 = 129,536 B (duplicated entries)
    for (int i = threadIdx.x; i < NE * 8; i += blockDim.x)
        sp[i] = g_projh[i];
    __syncthreads();

    const char* spb = reinterpret_cast<const char*>(sp);

    const int lane = threadIdx.x & 31;
    const int warp = threadIdx.x >> 5;
    const int sub  = lane & 7;        // position within 8-lane group
    const int grp  = lane >> 3;       // group id 0..3
    // Odd groups read copy B (banks 16..31), even groups copy A (banks 0..15):
    // half-warp LDS phases become deterministically conflict-free.
    const int par  = (grp & 1) * 64 + sub * 8;

    const int warpsTotal = gridDim.x * (blockDim.x >> 5);
    const int gwarp = blockIdx.x * (blockDim.x >> 5) + warp;

    for (int base = gwarp * 32; base < n; base += warpsTotal * 32) {
        // Phase A: coalesced per-lane index loads; pack 3 table indices into one int.
        int r = base + lane;
        int pk = 0, dd = 0;
        if (r < n) {
            int i1 = dow[r] * 24 + sex[r] * 12 + month[r];   // 0..167  (8 bits)
            int t2 = tim[r] * 31 + day[r];                   // 0..743  (10 bits)
            int a3 = age[r];                                 // 0..99   (7 bits)
            pk = i1 | (t2 << 8) | (a3 << 18);
            dd = dest[r];
        }

        // Phase B: 8 sub-iterations; each processes 4 rows with 8 lanes/row.
        #pragma unroll
        for (int s = 0; s < 8; s++) {
            int src = s * 4 + grp;
            int pks = __shfl_sync(0xffffffffu, pk, src);
            int dds = __shfl_sync(0xffffffffu, dd, src);
            int j1 = pks & 255;
            int j2 = N_T1 + ((pks >> 8) & 1023);
            int j3 = N_T1 + N_T2 + ((pks >> 18) & 127);

            // Each lane reads 8 B (4 halves) of its row's entry; conflict-free.
            uint2 A = *reinterpret_cast<const uint2*>(spb + j1 * 128 + par);
            uint2 C = *reinterpret_cast<const uint2*>(spb + j2 * 128 + par);
            uint2 E = *reinterpret_cast<const uint2*>(spb + j3 * 128 + par);
            // 8 lanes x 16 B = one full 128 B item row: 1 line per row.
            float4 v = __ldg(item4 + (size_t)dds * 8 + sub);

            float2 a0 = __half22float2(*reinterpret_cast<const __half2*>(&A.x));
            float2 a1 = __half22float2(*reinterpret_cast<const __half2*>(&A.y));
            float2 c0 = __half22float2(*reinterpret_cast<const __half2*>(&C.x));
            float2 c1 = __half22float2(*reinterpret_cast<const __half2*>(&C.y));
            float2 e0 = __half22float2(*reinterpret_cast<const __half2*>(&E.x));
            float2 e1 = __half22float2(*reinterpret_cast<const __half2*>(&E.y));

            float p;
            p =          (a0.x + c0.x + e0.x) * v.x;
            p = fmaf(a0.y + c0.y + e0.y, v.y, p);
            p = fmaf(a1.x + c1.x + e1.x, v.z, p);
            p = fmaf(a1.y + c1.y + e1.y, v.w, p);

            // Reduce across the 8-lane group.
            p += __shfl_xor_sync(0xffffffffu, p, 4);
            p += __shfl_xor_sync(0xffffffffu, p, 2);
            p += __shfl_xor_sync(0xffffffffu, p, 1);

            int row = base + src;
            if (sub == 0 && row < n)
                out[row] = p;
        }
    }
}

extern "C" void kernel_launch(void* const* d_in, const int* in_sizes, int n_in,
                              void* d_out, int out_size) {
    // Input order: dayofweek, time, sex, age, month, day, destination,
    // emb_dow, emb_time, emb_sex, emb_age, emb_month, emb_day, W, b, item_table
    const int* dow   = (const int*)d_in[0];
    const int* tim   = (const int*)d_in[1];
    const int* sex   = (const int*)d_in[2];
    const int* age   = (const int*)d_in[3];
    const int* month = (const int*)d_in[4];
    const int* day   = (const int*)d_in[5];
    const int* dest  = (const int*)d_in[6];
    const float* emb_dow   = (const float*)d_in[7];
    const float* emb_time  = (const float*)d_in[8];
    const float* emb_sex   = (const float*)d_in[9];
    const float* emb_age   = (const float*)d_in[10];
    const float* emb_month = (const float*)d_in[11];
    const float* emb_day   = (const float*)d_in[12];
    const float* W = (const float*)d_in[13];
    const float* b = (const float*)d_in[14];
    const float4* item4 = (const float4*)d_in[15];
    float* out = (float*)d_out;
    int n = in_sizes[0];

    // 1) Build fused pre-projected fp16 tables (1012 x 32, duplicated per entry).
    int pre_threads = NE * 32;
    precompute_kernel<<<(pre_threads + 255) / 256, 256>>>(
        emb_dow, emb_time, emb_sex, emb_age, emb_month, emb_day, W, b);

    // 2) Main gather + dot kernel. 129,536 B dynamic smem -> opt-in required.
    int smem_bytes = NE * 8 * (int)sizeof(uint4);
    cudaFuncSetAttribute(mf_main_kernel,
                         cudaFuncAttributeMaxDynamicSharedMemorySize, smem_bytes);
    mf_main_kernel<<<152, 1024, smem_bytes>>>(
        dow, tim, sex, age, month, day, dest, item4, out, n);
}